// round 10
// baseline (speedup 1.0000x reference)
#include <cuda_runtime.h>
#include <cuda_fp16.h>
#include <stdint.h>
#include <math.h>

#define BATCH 2
#define LA 4096
#define LB 4096
#define EMB 1024
#define HID 1024
#define MTOT (BATCH * LA)
#define MALL (2 * MTOT)   // both MLPs merged: 16384 rows

typedef __half h16;

// ---------------- scratch (device globals: no alloc allowed) ----------------
__device__ h16 g_xh[(size_t)MALL * EMB], g_xl[(size_t)MALL * EMB];
__device__ h16 g_w1h[(size_t)HID * EMB], g_w1l[(size_t)HID * EMB];
__device__ h16 g_w2h[(size_t)HID * HID], g_w2l[(size_t)HID * HID];
__device__ h16 g_w3h[(size_t)HID * HID], g_w3l[(size_t)HID * HID];
__device__ h16 g_t1h[(size_t)MALL * HID], g_t1l[(size_t)MALL * HID];
__device__ h16 g_t2h[(size_t)MALL * HID], g_t2l[(size_t)MALL * HID];
__device__ h16 g_fh[(size_t)MALL * HID], g_fl[(size_t)MALL * HID];  // fa | fb
__device__ h16 g_x1t[(size_t)BATCH * EMB * LA];
__device__ h16 g_x2t[(size_t)BATCH * EMB * LB];
__device__ float g_S[(size_t)BATCH * LA * LB];
__device__ h16 g_pr[(size_t)BATCH * LA * LB];   // row-softmax(S)
__device__ h16 g_pc[(size_t)BATCH * LB * LA];   // col-softmax(S)^T
__device__ float g_mcol[BATCH * LB], g_izcol[BATCH * LB];

// ---------------- ptx helpers ------------------------------------------------
__device__ __forceinline__ uint32_t smem_u32(const void* p) {
  uint32_t a;
  asm("{ .reg .u64 t; cvta.to.shared.u64 t, %1; cvt.u32.u64 %0, t; }"
      : "=r"(a) : "l"(p));
  return a;
}
__device__ __forceinline__ void cp16(uint32_t d, const void* s) {
  asm volatile("cp.async.cg.shared.global [%0], [%1], 16;" :: "r"(d), "l"(s));
}
__device__ __forceinline__ void cp_commit() {
  asm volatile("cp.async.commit_group;");
}
template <int N>
__device__ __forceinline__ void cp_wait() {
  asm volatile("cp.async.wait_group %0;" :: "n"(N));
}
__device__ __forceinline__ void ldsm4(uint32_t* r, uint32_t a) {
  asm volatile("ldmatrix.sync.aligned.m8n8.x4.shared.b16 {%0,%1,%2,%3}, [%4];"
               : "=r"(r[0]), "=r"(r[1]), "=r"(r[2]), "=r"(r[3]) : "r"(a));
}
__device__ __forceinline__ void mma16816(float* d, const uint32_t* a, const uint32_t* b) {
  asm volatile(
      "mma.sync.aligned.m16n8k16.row.col.f32.f16.f16.f32 "
      "{%0,%1,%2,%3}, {%4,%5,%6,%7}, {%8,%9}, {%0,%1,%2,%3};"
      : "+f"(d[0]), "+f"(d[1]), "+f"(d[2]), "+f"(d[3])
      : "r"(a[0]), "r"(a[1]), "r"(a[2]), "r"(a[3]), "r"(b[0]), "r"(b[1]));
}

__device__ __forceinline__ void split_store(h16* oh, h16* ol, size_t o, float v) {
  h16 h = __float2half_rn(v);
  oh[o] = h;
  ol[o] = __float2half_rn(v - __half2float(h));
}
__device__ __forceinline__ void split2_store(h16* oh, h16* ol, size_t o,
                                             float v0, float v1) {
  h16 h0 = __float2half_rn(v0), h1 = __float2half_rn(v1);
  __half2 hp; hp.x = h0; hp.y = h1;
  __half2 lp;
  lp.x = __float2half_rn(v0 - __half2float(h0));
  lp.y = __float2half_rn(v1 - __half2float(h1));
  *(__half2*)(oh + o) = hp;
  *(__half2*)(ol + o) = lp;
}

// ---------------- mma.sync GEMM core: C[128 x NT] = A @ B^T ------------------
// PASSES=3: A pair, B pair (AhBh + AhBl + AlBh).
// PASSES=2: A pair, B single (AhBh + AlBh).
// PASSES=1: A single, B single (AhBh).
// NT in {128, 256}. 3-stage cp.async pipeline, ONE __syncthreads per k-chunk.
static constexpr int LDM = 80;        // smem bytes per 32-h16 row (padded)

template <int PASSES, int NT>
static constexpr int smem_stage() {
  return ((PASSES >= 2) ? 2 : 1) * 128 * LDM + ((PASSES == 3) ? 2 : 1) * NT * LDM;
}
template <int PASSES, int NT>
static constexpr int smem_total() { return 3 * smem_stage<PASSES, NT>(); }

template <int EPI, int PASSES, int NT>
__device__ __forceinline__ void gemm_core(
    const h16* __restrict__ Ah, const h16* __restrict__ Al,
    const h16* __restrict__ Bh, const h16* __restrict__ Bl,
    int K, float* __restrict__ C, h16* __restrict__ Oh, h16* __restrict__ Ol,
    const float* __restrict__ bias, int ldc) {
  constexpr int NTA = (PASSES >= 2) ? 2 : 1;
  constexpr int NTB = (PASSES == 3) ? 2 : 1;
  constexpr int TA = 128 * LDM;
  constexpr int TB = NT * LDM;
  constexpr int STG = NTA * TA + NTB * TB;
  constexpr int AROWS = NTA * 128;
  constexpr int TROWS = AROWS + NTB * NT;
  constexpr int RPT = TROWS / 256;      // loader rows per thread (1..3)
  constexpr int JN = NT / 64;           // B j-frags per warp (2 or 4)
  extern __shared__ char smem[];
  const uint32_t sb = smem_u32(smem);
  const int tid = threadIdx.x;
  const int lane = tid & 31;
  const int wm = (tid >> 5) >> 2;   // 0..1
  const int wn = (tid >> 5) & 3;    // 0..3
  const size_t bm = (size_t)blockIdx.y * 128, bn = (size_t)blockIdx.x * NT;

  // -------- generalized loader: virtual rows [Ah | Al? | Bh | Bl?] ----------
  const h16* lp[RPT];
  uint32_t ls[RPT];
#pragma unroll
  for (int r = 0; r < RPT; r++) {
    const int vr = tid + r * 256;
    const h16* base;
    size_t row;
    if (vr < 128) { base = Ah; row = bm + vr; }
    else if (NTA == 2 && vr < 256) { base = Al; row = bm + (vr - 128); }
    else {
      const int rb = vr - AROWS;
      if (rb < NT) { base = Bh; row = bn + rb; }
      else         { base = Bl; row = bn + (rb - NT); }
    }
    lp[r] = base + row * (size_t)K;
    ls[r] = sb + (uint32_t)vr * LDM;
  }

#define LOADST(c, s)                                                     \
  do {                                                                   \
    const uint32_t so_ = (uint32_t)(s) * STG;                            \
    const size_t ko_ = (size_t)(c) * 32;                                 \
    _Pragma("unroll") for (int r_ = 0; r_ < RPT; r_++)                   \
      _Pragma("unroll") for (int ch_ = 0; ch_ < 4; ch_++)                \
          cp16(ls[r_] + so_ + ch_ * 16, lp[r_] + ko_ + ch_ * 8);         \
    cp_commit();                                                         \
  } while (0)

  // -------- fragment smem addresses (stage 0, kstep 0) ----------------------
  uint32_t aAh[4], aAl[4], aBh[JN], aBl[JN];
#pragma unroll
  for (int i = 0; i < 4; i++) {
    int row = wm * 64 + i * 16 + (lane & 15);
    uint32_t off = (uint32_t)(row * LDM + (lane >> 4) * 16);
    aAh[i] = sb + off;
    aAl[i] = sb + TA + off;
  }
#pragma unroll
  for (int j = 0; j < JN; j++) {
    int row = wn * (NT / 4) + j * 16 + (lane & 7) + ((lane >> 4) & 1) * 8;
    uint32_t off = (uint32_t)(row * LDM + ((lane >> 3) & 1) * 16);
    aBh[j] = sb + NTA * TA + off;
    aBl[j] = sb + NTA * TA + TB + off;
  }

  float acc[4][2 * JN][4];
#pragma unroll
  for (int i = 0; i < 4; i++)
#pragma unroll
    for (int j = 0; j < 2 * JN; j++)
#pragma unroll
      for (int r = 0; r < 4; r++) acc[i][j][r] = 0.f;

  const int NC = K >> 5;
  LOADST(0, 0);
  LOADST(1, 1);
  for (int c = 0; c < NC; c++) {
    if (c + 1 < NC) cp_wait<1>(); else cp_wait<0>();
    __syncthreads();
    if (c + 2 < NC) LOADST(c + 2, (c + 2) % 3);
    const uint32_t sbase = (uint32_t)(c % 3) * STG;
#pragma unroll
    for (int ks = 0; ks < 2; ks++) {
      const uint32_t soff = sbase + ks * 32;
      uint32_t fAh[4][4], fAl[4][4];
#pragma unroll
      for (int i = 0; i < 4; i++) {
        ldsm4(fAh[i], aAh[i] + soff);
        if (PASSES >= 2) ldsm4(fAl[i], aAl[i] + soff);
      }
#pragma unroll
      for (int j = 0; j < JN; j++) {
        uint32_t fBh[4], fBl[4];
        ldsm4(fBh, aBh[j] + soff);
        if (PASSES == 3) ldsm4(fBl, aBl[j] + soff);
#pragma unroll
        for (int i = 0; i < 4; i++)
#pragma unroll
          for (int hh = 0; hh < 2; hh++) {
            float* d = acc[i][j * 2 + hh];
            mma16816(d, fAh[i], &fBh[hh * 2]);
            if (PASSES == 3) mma16816(d, fAh[i], &fBl[hh * 2]);
            if (PASSES >= 2) mma16816(d, fAl[i], &fBh[hh * 2]);
          }
      }
    }
  }
#undef LOADST

  // epilogue
  const int l4 = lane >> 2, l2 = (lane & 3) * 2;
#pragma unroll
  for (int i = 0; i < 4; i++) {
#pragma unroll
    for (int j = 0; j < 2 * JN; j++) {
      const size_t row = bm + wm * 64 + i * 16 + l4;
      const size_t col = bn + wn * (NT / 4) + j * 8 + l2;
      float* a = acc[i][j];
      const size_t o = row * (size_t)ldc + col;
      if (EPI == 0) {
        float2 v0; v0.x = a[0]; v0.y = a[1];
        float2 v1; v1.x = a[2]; v1.y = a[3];
        *(float2*)(C + o) = v0;
        *(float2*)(C + o + 8 * (size_t)ldc) = v1;
      } else {
        float2 bv = *(const float2*)(bias + col);
        split2_store(Oh, Ol, o, fmaxf(a[0] + bv.x, 0.f), fmaxf(a[1] + bv.y, 0.f));
        split2_store(Oh, Ol, o + 8 * (size_t)ldc,
                     fmaxf(a[2] + bv.x, 0.f), fmaxf(a[3] + bv.y, 0.f));
      }
    }
  }
}

// generic wrapper (per-batch strides)
template <int EPI, int PASSES, int NT>
__global__ void __launch_bounds__(256, 1) gemm_mma(
    const h16* Ah, const h16* Al, const h16* Bh, const h16* Bl,
    int K, long long sA, long long sB,
    float* C, h16* Oh, h16* Ol, const float* bias, long long sC, int ldc) {
  const size_t b = blockIdx.z;
  gemm_core<EPI, PASSES, NT>(
      Ah + b * sA, (PASSES >= 2) ? Al + b * sA : nullptr, Bh + b * sB,
      (PASSES == 3) ? Bl + b * sB : nullptr, K,
      (EPI == 0) ? C + b * sC : nullptr,
      (EPI == 1) ? Oh + b * sC : nullptr,
      (EPI == 1) ? Ol + b * sC : nullptr, bias, ldc);
}

// fused beta+alpha, 1-pass NT=128: z=0,1 -> beta batches; z=2,3 -> alpha
__global__ void __launch_bounds__(256, 1) attn_fused(
    const h16* __restrict__ x2t, const h16* __restrict__ x1t,
    float* __restrict__ beta, float* __restrict__ alpha) {
  const int z = blockIdx.z;
  const h16 *A, *Bh;
  float* C;
  if (z < 2) {
    A = g_pr + (size_t)z * LA * LB;
    Bh = x2t + (size_t)z * EMB * LB;
    C = beta + (size_t)z * LA * EMB;
  } else {
    const int b = z - 2;
    A = g_pc + (size_t)b * LB * LA;
    Bh = x1t + (size_t)b * EMB * LA;
    C = alpha + (size_t)b * LB * EMB;
  }
  gemm_core<0, 1, 128>(A, nullptr, Bh, nullptr, LB, C, nullptr, nullptr, nullptr, EMB);
}

// ---------------- conversion kernels -----------------------------------------
// fused: x -> (hi,lo) row-major pair AND transposed fp16, single read of x.
// block (32,8); tile 64 rows (L dim) x 32 cols (E dim).
__global__ void k_prep(const float* __restrict__ in, h16* __restrict__ oh,
                       h16* __restrict__ ol, h16* __restrict__ ot, int L) {
  __shared__ float t[64][33];
  const int b = blockIdx.z;
  const int r0 = blockIdx.y * 64, c0 = blockIdx.x * 32;
  const int tx = threadIdx.x, ty = threadIdx.y;
  const float* pin = in + (size_t)b * L * EMB;
#pragma unroll
  for (int k = 0; k < 8; k++) {
    const int r = r0 + ty + 8 * k;
    float v = pin[(size_t)r * EMB + c0 + tx];
    t[ty + 8 * k][tx] = v;
    split_store(oh, ol, (size_t)(b * L + r) * EMB + c0 + tx, v);
  }
  __syncthreads();
#pragma unroll
  for (int k = 0; k < 4; k++) {
    const int c = c0 + ty + 8 * k;
    __half2 h = __floats2half2_rn(t[2 * tx][ty + 8 * k], t[2 * tx + 1][ty + 8 * k]);
    *(__half2*)(ot + (size_t)b * EMB * L + (size_t)c * L + r0 + 2 * tx) = h;
  }
}

__global__ void k_tsplit(const float* __restrict__ in, h16* __restrict__ oh,
                         h16* __restrict__ ol, int R, int Cc) {
  __shared__ float t[32][33];
  const int r0 = blockIdx.y * 32, c0 = blockIdx.x * 32;
  const int tx = threadIdx.x, ty = threadIdx.y;
#pragma unroll
  for (int k = 0; k < 4; k++)
    t[ty + 8 * k][tx] = in[(size_t)(r0 + ty + 8 * k) * Cc + c0 + tx];
  __syncthreads();
#pragma unroll
  for (int k = 0; k < 4; k++) {
    float v = t[tx][ty + 8 * k];
    size_t o = (size_t)(c0 + ty + 8 * k) * R + r0 + tx;
    split_store(oh, ol, o, v);
  }
}

// ---------------- softmax -----------------------------------------------------
__device__ __forceinline__ void olcomb(float& m, float& z, float m2, float z2) {
  if (m2 > m) { z = z * __expf(m - m2) + z2; m = m2; }
  else        { z = z + z2 * __expf(m2 - m); }
}
__device__ __forceinline__ void olup(float& m, float& z, float v) {
  if (v > m) { z = z * __expf(m - v) + 1.f; m = v; }
  else       { z += __expf(v - m); }
}

// fused: row stats + exp-normalize -> g_pr (fp16), float4/uint2 vectorized
__global__ void row_softmax_kernel() {
  const int row = blockIdx.x;
  const float4* s4 = (const float4*)(g_S + (size_t)row * LB);
  float m = -3.0e38f, z = 0.f;
  for (int j = threadIdx.x; j < LB / 4; j += 256) {
    float4 v = s4[j];
    olup(m, z, v.x); olup(m, z, v.y); olup(m, z, v.z); olup(m, z, v.w);
  }
  __shared__ float sm[256], sz[256];
  sm[threadIdx.x] = m; sz[threadIdx.x] = z;
  __syncthreads();
  for (int st = 128; st > 0; st >>= 1) {
    if (threadIdx.x < st) {
      float m1 = sm[threadIdx.x], z1 = sz[threadIdx.x];
      olcomb(m1, z1, sm[threadIdx.x + st], sz[threadIdx.x + st]);
      sm[threadIdx.x] = m1; sz[threadIdx.x] = z1;
    }
    __syncthreads();
  }
  const float mm = sm[0], iz = 1.f / sz[0];
  uint2* p = (uint2*)(g_pr + (size_t)row * LB);
  for (int j = threadIdx.x; j < LB / 4; j += 256) {
    float4 v = s4[j];
    __half2 h01 = __floats2half2_rn(__expf(v.x - mm) * iz, __expf(v.y - mm) * iz);
    __half2 h23 = __floats2half2_rn(__expf(v.z - mm) * iz, __expf(v.w - mm) * iz);
    uint2 w;
    w.x = *(uint32_t*)&h01;
    w.y = *(uint32_t*)&h23;
    p[j] = w;
  }
}

__global__ void col_stats_kernel() {
  const int b = blockIdx.y;
  const int col = blockIdx.x * 128 + threadIdx.x;
  const float* s = g_S + (size_t)b * LA * LB + col;
  float m = -3.0e38f, z = 0.f;
  for (int i = threadIdx.y; i < LA; i += 8) {
    float v = s[(size_t)i * LB];
    olup(m, z, v);
  }
  __shared__ float sm[8][128], sz[8][128];
  sm[threadIdx.y][threadIdx.x] = m; sz[threadIdx.y][threadIdx.x] = z;
  __syncthreads();
  if (threadIdx.y == 0) {
#pragma unroll
    for (int y = 1; y < 8; y++) olcomb(m, z, sm[y][threadIdx.x], sz[y][threadIdx.x]);
    g_mcol[b * LB + col] = m;
    g_izcol[b * LB + col] = 1.f / z;
  }
}

// col-softmax + transpose -> g_pc (fp16). block (32,8); tile 64 i x 32 j.
__global__ void k_pcolT() {
  __shared__ float t[64][33];
  const int b = blockIdx.z;
  const int i0 = blockIdx.y * 64, j0 = blockIdx.x * 32;
  const int tx = threadIdx.x, ty = threadIdx.y;
  const float* S = g_S + (size_t)b * LA * LB;
#pragma unroll
  for (int k = 0; k < 8; k++)
    t[ty + 8 * k][tx] = S[(size_t)(i0 + ty + 8 * k) * LB + j0 + tx];
  __syncthreads();
#pragma unroll
  for (int k = 0; k < 4; k++) {
    const int j = j0 + ty + 8 * k;
    const float m = g_mcol[b * LB + j], iz = g_izcol[b * LB + j];
    float p0 = __expf(t[2 * tx][ty + 8 * k] - m) * iz;
    float p1 = __expf(t[2 * tx + 1][ty + 8 * k] - m) * iz;
    __half2 h = __floats2half2_rn(p0, p1);
    *(__half2*)(g_pc + (size_t)b * LB * LA + (size_t)j * LA + i0 + 2 * tx) = h;
  }
}

// ---------------- launch -----------------------------------------------------
#define GSA(T, v, sym) T* v; cudaGetSymbolAddress((void**)&v, sym)

extern "C" void kernel_launch(void* const* d_in, const int* in_sizes, int n_in,
                              void* d_out, int out_size) {
  const float* x1 = (const float*)d_in[0];
  const float* x2 = (const float*)d_in[1];
  const float* W1 = (const float*)d_in[2];
  const float* b1 = (const float*)d_in[3];
  const float* W2 = (const float*)d_in[4];
  const float* b2 = (const float*)d_in[5];
  const float* W3 = (const float*)d_in[6];
  const float* b3 = (const float*)d_in[7];
  float* out = (float*)d_out;
  float* alpha_out = out;                             // [B, LB, EMB]
  float* beta_out = out + (size_t)BATCH * LB * EMB;   // [B, LA, EMB]

  GSA(h16, xh, g_xh); GSA(h16, xl, g_xl);
  GSA(h16, w1h, g_w1h); GSA(h16, w1l, g_w1l);
  GSA(h16, w2h, g_w2h); GSA(h16, w2l, g_w2l);
  GSA(h16, w3h, g_w3h); GSA(h16, w3l, g_w3l);
  GSA(h16, t1h, g_t1h); GSA(h16, t1l, g_t1l);
  GSA(h16, t2h, g_t2h); GSA(h16, t2l, g_t2l);
  GSA(h16, fh, g_fh); GSA(h16, fl, g_fl);
  GSA(h16, x1t, g_x1t); GSA(h16, x2t, g_x2t);
  GSA(float, S, g_S);

  constexpr int SM_MLP = smem_total<3, 128>();   // 122880
  constexpr int SM_SCR = smem_total<2, 256>();   // 122880
  constexpr int SM_ATT = smem_total<1, 128>();   // 61440
  cudaFuncSetAttribute(gemm_mma<1, 3, 128>, cudaFuncAttributeMaxDynamicSharedMemorySize, SM_MLP);
  cudaFuncSetAttribute(gemm_mma<0, 2, 256>, cudaFuncAttributeMaxDynamicSharedMemorySize, SM_SCR);
  cudaFuncSetAttribute(attn_fused, cudaFuncAttributeMaxDynamicSharedMemorySize, SM_ATT);

  const size_t nx = (size_t)MTOT * EMB;
  dim3 t8(32, 8);

  // fused input prep: x1 -> rows [0, 8192) + x1t ; x2 -> rows [8192, 16384) + x2t
  k_prep<<<dim3(EMB / 32, LA / 64, BATCH), t8>>>(x1, xh, xl, x1t, LA);
  k_prep<<<dim3(EMB / 32, LB / 64, BATCH), t8>>>(x2, xh + nx, xl + nx, x2t, LB);
  k_tsplit<<<dim3(HID / 32, EMB / 32), t8>>>(W1, w1h, w1l, EMB, HID);
  k_tsplit<<<dim3(HID / 32, HID / 32), t8>>>(W2, w2h, w2l, HID, HID);
  k_tsplit<<<dim3(HID / 32, HID / 32), t8>>>(W3, w3h, w3l, HID, HID);

  // merged MLP (both inputs, both batches): M = 16384, 3-pass, NT=128
  dim3 gMLP(HID / 128, MALL / 128, 1);  // (8, 128) = 1024 CTAs
  gemm_mma<1, 3, 128><<<gMLP, 256, SM_MLP>>>(xh, xl, w1h, w1l, EMB, 0, 0,
                                             nullptr, t1h, t1l, b1, 0, HID);
  gemm_mma<1, 3, 128><<<gMLP, 256, SM_MLP>>>(t1h, t1l, w2h, w2l, HID, 0, 0,
                                             nullptr, t2h, t2l, b2, 0, HID);
  gemm_mma<1, 3, 128><<<gMLP, 256, SM_MLP>>>(t2h, t2l, w3h, w3l, HID, 0, 0,
                                             nullptr, fh, fl, b3, 0, HID);

  // scores: S[b] = fa[b] @ fb[b]^T, 2-pass, NT=256
  const h16* fah = fh;
  const h16* fal = fl;
  const h16* fbh = fh + (size_t)MTOT * HID;
  gemm_mma<0, 2, 256><<<dim3(LB / 256, LA / 128, BATCH), 256, SM_SCR>>>(
      fah, fal, fbh, nullptr, HID, (long long)LA * HID, (long long)LB * HID,
      S, nullptr, nullptr, nullptr, (long long)LA * LB, LB);

  // softmax: fused row stats+normalize; col stats then transpose-normalize
  row_softmax_kernel<<<BATCH * LA, 256>>>();
  col_stats_kernel<<<dim3(LB / 128, BATCH), dim3(128, 8)>>>();
  k_pcolT<<<dim3(LB / 32, LA / 64, BATCH), t8>>>();

  // fused beta+alpha (1-pass, NT=128): z=0,1 beta; z=2,3 alpha -> 1024 CTAs
  attn_fused<<<dim3(EMB / 128, LA / 128, 4), 256, SM_ATT>>>(
      x2t, x1t, beta_out, alpha_out);
}

// round 12
// speedup vs baseline: 1.0248x; 1.0248x over previous
#include <cuda_runtime.h>
#include <cuda_fp16.h>
#include <stdint.h>
#include <math.h>

#define BATCH 2
#define LA 4096
#define LB 4096
#define EMB 1024
#define HID 1024
#define MTOT (BATCH * LA)
#define MALL (2 * MTOT)   // both MLPs merged: 16384 rows

typedef __half h16;

// ---------------- scratch (device globals: no alloc allowed) ----------------
__device__ h16 g_xh[(size_t)MALL * EMB], g_xl[(size_t)MALL * EMB];
__device__ h16 g_w1h[(size_t)HID * EMB], g_w1l[(size_t)HID * EMB];
__device__ h16 g_w2h[(size_t)HID * HID], g_w2l[(size_t)HID * HID];
__device__ h16 g_w3h[(size_t)HID * HID], g_w3l[(size_t)HID * HID];
__device__ h16 g_t1h[(size_t)MALL * HID], g_t1l[(size_t)MALL * HID];
__device__ h16 g_t2h[(size_t)MALL * HID], g_t2l[(size_t)MALL * HID];
__device__ h16 g_fh[(size_t)MALL * HID], g_fl[(size_t)MALL * HID];  // fa | fb
__device__ h16 g_x1t[(size_t)BATCH * EMB * LA];
__device__ h16 g_x2t[(size_t)BATCH * EMB * LB];
__device__ float g_S[(size_t)BATCH * LA * LB];
__device__ h16 g_pr[(size_t)BATCH * LA * LB];   // row-softmax(S)
__device__ h16 g_pc[(size_t)BATCH * LB * LA];   // col-softmax(S)^T
__device__ float g_mcol[BATCH * LB], g_izcol[BATCH * LB];

// ---------------- ptx helpers ------------------------------------------------
__device__ __forceinline__ uint32_t smem_u32(const void* p) {
  uint32_t a;
  asm("{ .reg .u64 t; cvta.to.shared.u64 t, %1; cvt.u32.u64 %0, t; }"
      : "=r"(a) : "l"(p));
  return a;
}
__device__ __forceinline__ void cp16(uint32_t d, const void* s) {
  asm volatile("cp.async.cg.shared.global [%0], [%1], 16;" :: "r"(d), "l"(s));
}
__device__ __forceinline__ void cp_commit() {
  asm volatile("cp.async.commit_group;");
}
template <int N>
__device__ __forceinline__ void cp_wait() {
  asm volatile("cp.async.wait_group %0;" :: "n"(N));
}
__device__ __forceinline__ void ldsm4(uint32_t* r, uint32_t a) {
  asm volatile("ldmatrix.sync.aligned.m8n8.x4.shared.b16 {%0,%1,%2,%3}, [%4];"
               : "=r"(r[0]), "=r"(r[1]), "=r"(r[2]), "=r"(r[3]) : "r"(a));
}
__device__ __forceinline__ void mma16816(float* d, const uint32_t* a, const uint32_t* b) {
  asm volatile(
      "mma.sync.aligned.m16n8k16.row.col.f32.f16.f16.f32 "
      "{%0,%1,%2,%3}, {%4,%5,%6,%7}, {%8,%9}, {%0,%1,%2,%3};"
      : "+f"(d[0]), "+f"(d[1]), "+f"(d[2]), "+f"(d[3])
      : "r"(a[0]), "r"(a[1]), "r"(a[2]), "r"(a[3]), "r"(b[0]), "r"(b[1]));
}

__device__ __forceinline__ void split_store(h16* oh, h16* ol, size_t o, float v) {
  h16 h = __float2half_rn(v);
  oh[o] = h;
  ol[o] = __float2half_rn(v - __half2float(h));
}
__device__ __forceinline__ void split2_store(h16* oh, h16* ol, size_t o,
                                             float v0, float v1) {
  h16 h0 = __float2half_rn(v0), h1 = __float2half_rn(v1);
  __half2 hp; hp.x = h0; hp.y = h1;
  __half2 lp;
  lp.x = __float2half_rn(v0 - __half2float(h0));
  lp.y = __float2half_rn(v1 - __half2float(h1));
  *(__half2*)(oh + o) = hp;
  *(__half2*)(ol + o) = lp;
}

// ---------------- mma.sync GEMM core: C[128 x NT] = A @ B^T ------------------
// PASSES=3: A pair, B pair (AhBh + AhBl + AlBh).
// PASSES=2: A pair, B single (AhBh + AlBh).
// PASSES=1: A single, B single (AhBh).
static constexpr int LDM = 80;        // smem bytes per 32-h16 row (padded)

template <int PASSES, int NT>
static constexpr int smem_stage() {
  return ((PASSES >= 2) ? 2 : 1) * 128 * LDM + ((PASSES == 3) ? 2 : 1) * NT * LDM;
}
template <int PASSES, int NT>
static constexpr int smem_total() { return 3 * smem_stage<PASSES, NT>(); }

template <int EPI, int PASSES, int NT>
__device__ __forceinline__ void gemm_core(
    const h16* __restrict__ Ah, const h16* __restrict__ Al,
    const h16* __restrict__ Bh, const h16* __restrict__ Bl,
    int K, float* __restrict__ C, h16* __restrict__ Oh, h16* __restrict__ Ol,
    const float* __restrict__ bias, int ldc) {
  constexpr int NTA = (PASSES >= 2) ? 2 : 1;
  constexpr int NTB = (PASSES == 3) ? 2 : 1;
  constexpr int TA = 128 * LDM;
  constexpr int TB = NT * LDM;
  constexpr int STG = NTA * TA + NTB * TB;
  constexpr int AROWS = NTA * 128;
  constexpr int TROWS = AROWS + NTB * NT;
  constexpr int RPT = (TROWS + 255) / 256;  // loader iterations (ceil!)
  constexpr int JN = NT / 64;               // B j-frags per warp
  extern __shared__ char smem[];
  const uint32_t sb = smem_u32(smem);
  const int tid = threadIdx.x;
  const int lane = tid & 31;
  const int wm = (tid >> 5) >> 2;   // 0..1
  const int wn = (tid >> 5) & 3;    // 0..3
  const size_t bm = (size_t)blockIdx.y * 128, bn = (size_t)blockIdx.x * NT;

  // -------- generalized loader: virtual rows [Ah | Al? | Bh | Bl?] ----------
  // Iteration r covers virtual row vr = tid + r*256; guard partial last iter.
  const h16* lp[RPT];
  uint32_t ls[RPT];
  bool lv[RPT];
#pragma unroll
  for (int r = 0; r < RPT; r++) {
    const int vr = tid + r * 256;
    lv[r] = (vr < TROWS);
    const h16* base;
    size_t row;
    if (vr < 128) { base = Ah; row = bm + vr; }
    else if (NTA == 2 && vr < 256) { base = Al; row = bm + (vr - 128); }
    else if (vr < TROWS) {
      const int rb = vr - AROWS;
      if (rb < NT) { base = Bh; row = bn + rb; }
      else         { base = Bl; row = bn + (rb - NT); }
    } else { base = Ah; row = bm; }  // dummy (guarded off)
    lp[r] = base + row * (size_t)K;
    ls[r] = sb + (uint32_t)((vr < TROWS ? vr : 0) * LDM);
  }

#define LOADST(c, s)                                                     \
  do {                                                                   \
    const uint32_t so_ = (uint32_t)(s) * STG;                            \
    const size_t ko_ = (size_t)(c) * 32;                                 \
    _Pragma("unroll") for (int r_ = 0; r_ < RPT; r_++)                   \
      if (lv[r_])                                                        \
        _Pragma("unroll") for (int ch_ = 0; ch_ < 4; ch_++)              \
            cp16(ls[r_] + so_ + ch_ * 16, lp[r_] + ko_ + ch_ * 8);       \
    cp_commit();                                                         \
  } while (0)

  // -------- fragment smem addresses (stage 0, kstep 0) ----------------------
  uint32_t aAh[4], aAl[4], aBh[JN], aBl[JN];
#pragma unroll
  for (int i = 0; i < 4; i++) {
    int row = wm * 64 + i * 16 + (lane & 15);
    uint32_t off = (uint32_t)(row * LDM + (lane >> 4) * 16);
    aAh[i] = sb + off;
    aAl[i] = sb + TA + off;
  }
#pragma unroll
  for (int j = 0; j < JN; j++) {
    int row = wn * (NT / 4) + j * 16 + (lane & 7) + ((lane >> 4) & 1) * 8;
    uint32_t off = (uint32_t)(row * LDM + ((lane >> 3) & 1) * 16);
    aBh[j] = sb + NTA * TA + off;
    aBl[j] = sb + NTA * TA + TB + off;
  }

  float acc[4][2 * JN][4];
#pragma unroll
  for (int i = 0; i < 4; i++)
#pragma unroll
    for (int j = 0; j < 2 * JN; j++)
#pragma unroll
      for (int r = 0; r < 4; r++) acc[i][j][r] = 0.f;

  const int NC = K >> 5;
  LOADST(0, 0);
  LOADST(1, 1);
  for (int c = 0; c < NC; c++) {
    if (c + 1 < NC) cp_wait<1>(); else cp_wait<0>();
    __syncthreads();
    if (c + 2 < NC) LOADST(c + 2, (c + 2) % 3);
    const uint32_t sbase = (uint32_t)(c % 3) * STG;
#pragma unroll
    for (int ks = 0; ks < 2; ks++) {
      const uint32_t soff = sbase + ks * 32;
      uint32_t fAh[4][4], fAl[4][4];
#pragma unroll
      for (int i = 0; i < 4; i++) {
        ldsm4(fAh[i], aAh[i] + soff);
        if (PASSES >= 2) ldsm4(fAl[i], aAl[i] + soff);
      }
#pragma unroll
      for (int j = 0; j < JN; j++) {
        uint32_t fBh[4], fBl[4];
        ldsm4(fBh, aBh[j] + soff);
        if (PASSES == 3) ldsm4(fBl, aBl[j] + soff);
#pragma unroll
        for (int i = 0; i < 4; i++)
#pragma unroll
          for (int hh = 0; hh < 2; hh++) {
            float* d = acc[i][j * 2 + hh];
            mma16816(d, fAh[i], &fBh[hh * 2]);
            if (PASSES == 3) mma16816(d, fAh[i], &fBl[hh * 2]);
            if (PASSES >= 2) mma16816(d, fAl[i], &fBh[hh * 2]);
          }
      }
    }
  }
#undef LOADST

  // epilogue
  const int l4 = lane >> 2, l2 = (lane & 3) * 2;
#pragma unroll
  for (int i = 0; i < 4; i++) {
#pragma unroll
    for (int j = 0; j < 2 * JN; j++) {
      const size_t row = bm + wm * 64 + i * 16 + l4;
      const size_t col = bn + wn * (NT / 4) + j * 8 + l2;
      float* a = acc[i][j];
      const size_t o = row * (size_t)ldc + col;
      if (EPI == 0) {
        float2 v0; v0.x = a[0]; v0.y = a[1];
        float2 v1; v1.x = a[2]; v1.y = a[3];
        *(float2*)(C + o) = v0;
        *(float2*)(C + o + 8 * (size_t)ldc) = v1;
      } else {
        float2 bv = *(const float2*)(bias + col);
        split2_store(Oh, Ol, o, fmaxf(a[0] + bv.x, 0.f), fmaxf(a[1] + bv.y, 0.f));
        split2_store(Oh, Ol, o + 8 * (size_t)ldc,
                     fmaxf(a[2] + bv.x, 0.f), fmaxf(a[3] + bv.y, 0.f));
      }
    }
  }
}

// generic wrapper (per-batch strides)
template <int EPI, int PASSES, int NT>
__global__ void __launch_bounds__(256, 1) gemm_mma(
    const h16* Ah, const h16* Al, const h16* Bh, const h16* Bl,
    int K, long long sA, long long sB,
    float* C, h16* Oh, h16* Ol, const float* bias, long long sC, int ldc) {
  const size_t b = blockIdx.z;
  gemm_core<EPI, PASSES, NT>(
      Ah + b * sA, (PASSES >= 2) ? Al + b * sA : nullptr, Bh + b * sB,
      (PASSES == 3) ? Bl + b * sB : nullptr, K,
      (EPI == 0) ? C + b * sC : nullptr,
      (EPI == 1) ? Oh + b * sC : nullptr,
      (EPI == 1) ? Ol + b * sC : nullptr, bias, ldc);
}

// fused beta+alpha, 1-pass NT=256: z=0,1 -> beta batches; z=2,3 -> alpha
__global__ void __launch_bounds__(256, 1) attn_fused(
    const h16* __restrict__ x2t, const h16* __restrict__ x1t,
    float* __restrict__ beta, float* __restrict__ alpha) {
  const int z = blockIdx.z;
  const h16 *A, *Bh;
  float* C;
  if (z < 2) {
    A = g_pr + (size_t)z * LA * LB;
    Bh = x2t + (size_t)z * EMB * LB;
    C = beta + (size_t)z * LA * EMB;
  } else {
    const int b = z - 2;
    A = g_pc + (size_t)b * LB * LA;
    Bh = x1t + (size_t)b * EMB * LA;
    C = alpha + (size_t)b * LB * EMB;
  }
  gemm_core<0, 1, 256>(A, nullptr, Bh, nullptr, LB, C, nullptr, nullptr, nullptr, EMB);
}

// ---------------- conversion kernels -----------------------------------------
// fused: x -> (hi,lo) row-major pair AND transposed fp16, single read of x.
__global__ void k_prep(const float* __restrict__ in, h16* __restrict__ oh,
                       h16* __restrict__ ol, h16* __restrict__ ot, int L) {
  __shared__ float t[64][33];
  const int b = blockIdx.z;
  const int r0 = blockIdx.y * 64, c0 = blockIdx.x * 32;
  const int tx = threadIdx.x, ty = threadIdx.y;
  const float* pin = in + (size_t)b * L * EMB;
#pragma unroll
  for (int k = 0; k < 8; k++) {
    const int r = r0 + ty + 8 * k;
    float v = pin[(size_t)r * EMB + c0 + tx];
    t[ty + 8 * k][tx] = v;
    split_store(oh, ol, (size_t)(b * L + r) * EMB + c0 + tx, v);
  }
  __syncthreads();
#pragma unroll
  for (int k = 0; k < 4; k++) {
    const int c = c0 + ty + 8 * k;
    __half2 h = __floats2half2_rn(t[2 * tx][ty + 8 * k], t[2 * tx + 1][ty + 8 * k]);
    *(__half2*)(ot + (size_t)b * EMB * L + (size_t)c * L + r0 + 2 * tx) = h;
  }
}

__global__ void k_tsplit(const float* __restrict__ in, h16* __restrict__ oh,
                         h16* __restrict__ ol, int R, int Cc) {
  __shared__ float t[32][33];
  const int r0 = blockIdx.y * 32, c0 = blockIdx.x * 32;
  const int tx = threadIdx.x, ty = threadIdx.y;
#pragma unroll
  for (int k = 0; k < 4; k++)
    t[ty + 8 * k][tx] = in[(size_t)(r0 + ty + 8 * k) * Cc + c0 + tx];
  __syncthreads();
#pragma unroll
  for (int k = 0; k < 4; k++) {
    float v = t[tx][ty + 8 * k];
    size_t o = (size_t)(c0 + ty + 8 * k) * R + r0 + tx;
    split_store(oh, ol, o, v);
  }
}

// ---------------- softmax -----------------------------------------------------
__device__ __forceinline__ void olcomb(float& m, float& z, float m2, float z2) {
  if (m2 > m) { z = z * __expf(m - m2) + z2; m = m2; }
  else        { z = z + z2 * __expf(m2 - m); }
}
__device__ __forceinline__ void olup(float& m, float& z, float v) {
  if (v > m) { z = z * __expf(m - v) + 1.f; m = v; }
  else       { z += __expf(v - m); }
}

// row softmax, register-cached 3-phase: 1 S read, 1 exp per element.
__global__ void row_softmax_kernel() {
  const int row = blockIdx.x;
  const float4* s4 = (const float4*)(g_S + (size_t)row * LB);
  float4 v[4];
#pragma unroll
  for (int q = 0; q < 4; q++) v[q] = s4[threadIdx.x + q * 256];

  float m = v[0].x;
#pragma unroll
  for (int q = 0; q < 4; q++)
    m = fmaxf(m, fmaxf(fmaxf(v[q].x, v[q].y), fmaxf(v[q].z, v[q].w)));
  __shared__ float sm[256];
  sm[threadIdx.x] = m;
  __syncthreads();
  for (int st = 128; st > 0; st >>= 1) {
    if (threadIdx.x < st)
      sm[threadIdx.x] = fmaxf(sm[threadIdx.x], sm[threadIdx.x + st]);
    __syncthreads();
  }
  const float mm = sm[0];
  __syncthreads();

  float z = 0.f;
#pragma unroll
  for (int q = 0; q < 4; q++) {
    v[q].x = __expf(v[q].x - mm); v[q].y = __expf(v[q].y - mm);
    v[q].z = __expf(v[q].z - mm); v[q].w = __expf(v[q].w - mm);
    z += (v[q].x + v[q].y) + (v[q].z + v[q].w);
  }
  __shared__ float sz[256];
  sz[threadIdx.x] = z;
  __syncthreads();
  for (int st = 128; st > 0; st >>= 1) {
    if (threadIdx.x < st)
      sz[threadIdx.x] += sz[threadIdx.x + st];
    __syncthreads();
  }
  const float iz = 1.f / sz[0];

  uint2* p = (uint2*)(g_pr + (size_t)row * LB);
#pragma unroll
  for (int q = 0; q < 4; q++) {
    __half2 h01 = __floats2half2_rn(v[q].x * iz, v[q].y * iz);
    __half2 h23 = __floats2half2_rn(v[q].z * iz, v[q].w * iz);
    uint2 w;
    w.x = *(uint32_t*)&h01;
    w.y = *(uint32_t*)&h23;
    p[threadIdx.x + q * 256] = w;
  }
}

__global__ void col_stats_kernel() {
  const int b = blockIdx.y;
  const int col = blockIdx.x * 128 + threadIdx.x;
  const float* s = g_S + (size_t)b * LA * LB + col;
  float m = -3.0e38f, z = 0.f;
  for (int i = threadIdx.y; i < LA; i += 8) {
    float v = s[(size_t)i * LB];
    olup(m, z, v);
  }
  __shared__ float sm[8][128], sz[8][128];
  sm[threadIdx.y][threadIdx.x] = m; sz[threadIdx.y][threadIdx.x] = z;
  __syncthreads();
  if (threadIdx.y == 0) {
#pragma unroll
    for (int y = 1; y < 8; y++) olcomb(m, z, sm[y][threadIdx.x], sz[y][threadIdx.x]);
    g_mcol[b * LB + col] = m;
    g_izcol[b * LB + col] = 1.f / z;
  }
}

// col-softmax + transpose -> g_pc (fp16). block (32,8); tile 64 i x 32 j.
__global__ void k_pcolT() {
  __shared__ float t[64][33];
  const int b = blockIdx.z;
  const int i0 = blockIdx.y * 64, j0 = blockIdx.x * 32;
  const int tx = threadIdx.x, ty = threadIdx.y;
  const float* S = g_S + (size_t)b * LA * LB;
#pragma unroll
  for (int k = 0; k < 8; k++)
    t[ty + 8 * k][tx] = S[(size_t)(i0 + ty + 8 * k) * LB + j0 + tx];
  __syncthreads();
#pragma unroll
  for (int k = 0; k < 4; k++) {
    const int j = j0 + ty + 8 * k;
    const float m = g_mcol[b * LB + j], iz = g_izcol[b * LB + j];
    float p0 = __expf(t[2 * tx][ty + 8 * k] - m) * iz;
    float p1 = __expf(t[2 * tx + 1][ty + 8 * k] - m) * iz;
    __half2 h = __floats2half2_rn(p0, p1);
    *(__half2*)(g_pc + (size_t)b * LB * LA + (size_t)j * LA + i0 + 2 * tx) = h;
  }
}

// ---------------- launch -----------------------------------------------------
#define GSA(T, v, sym) T* v; cudaGetSymbolAddress((void**)&v, sym)

extern "C" void kernel_launch(void* const* d_in, const int* in_sizes, int n_in,
                              void* d_out, int out_size) {
  const float* x1 = (const float*)d_in[0];
  const float* x2 = (const float*)d_in[1];
  const float* W1 = (const float*)d_in[2];
  const float* b1 = (const float*)d_in[3];
  const float* W2 = (const float*)d_in[4];
  const float* b2 = (const float*)d_in[5];
  const float* W3 = (const float*)d_in[6];
  const float* b3 = (const float*)d_in[7];
  float* out = (float*)d_out;
  float* alpha_out = out;                             // [B, LB, EMB]
  float* beta_out = out + (size_t)BATCH * LB * EMB;   // [B, LA, EMB]

  GSA(h16, xh, g_xh); GSA(h16, xl, g_xl);
  GSA(h16, w1h, g_w1h); GSA(h16, w1l, g_w1l);
  GSA(h16, w2h, g_w2h); GSA(h16, w2l, g_w2l);
  GSA(h16, w3h, g_w3h); GSA(h16, w3l, g_w3l);
  GSA(h16, t1h, g_t1h); GSA(h16, t1l, g_t1l);
  GSA(h16, t2h, g_t2h); GSA(h16, t2l, g_t2l);
  GSA(h16, fh, g_fh); GSA(h16, fl, g_fl);
  GSA(h16, x1t, g_x1t); GSA(h16, x2t, g_x2t);
  GSA(float, S, g_S);

  constexpr int SM3 = smem_total<3, 256>();   // 184320
  constexpr int SM2 = smem_total<2, 256>();   // 122880
  constexpr int SM1 = smem_total<1, 256>();   // 92160
  cudaFuncSetAttribute(gemm_mma<1, 3, 256>, cudaFuncAttributeMaxDynamicSharedMemorySize, SM3);
  cudaFuncSetAttribute(gemm_mma<0, 2, 256>, cudaFuncAttributeMaxDynamicSharedMemorySize, SM2);
  cudaFuncSetAttribute(attn_fused, cudaFuncAttributeMaxDynamicSharedMemorySize, SM1);

  const size_t nx = (size_t)MTOT * EMB;
  dim3 t8(32, 8);

  // fused input prep: x1 -> rows [0, 8192) + x1t ; x2 -> rows [8192, 16384) + x2t
  k_prep<<<dim3(EMB / 32, LA / 64, BATCH), t8>>>(x1, xh, xl, x1t, LA);
  k_prep<<<dim3(EMB / 32, LB / 64, BATCH), t8>>>(x2, xh + nx, xl + nx, x2t, LB);
  k_tsplit<<<dim3(HID / 32, EMB / 32), t8>>>(W1, w1h, w1l, EMB, HID);
  k_tsplit<<<dim3(HID / 32, HID / 32), t8>>>(W2, w2h, w2l, HID, HID);
  k_tsplit<<<dim3(HID / 32, HID / 32), t8>>>(W3, w3h, w3l, HID, HID);

  // merged MLP (both inputs, both batches): M = 16384, 3-pass, NT=256
  dim3 gMLP(HID / 256, MALL / 128, 1);  // (4, 128) = 512 CTAs
  gemm_mma<1, 3, 256><<<gMLP, 256, SM3>>>(xh, xl, w1h, w1l, EMB, 0, 0,
                                          nullptr, t1h, t1l, b1, 0, HID);
  gemm_mma<1, 3, 256><<<gMLP, 256, SM3>>>(t1h, t1l, w2h, w2l, HID, 0, 0,
                                          nullptr, t2h, t2l, b2, 0, HID);
  gemm_mma<1, 3, 256><<<gMLP, 256, SM3>>>(t2h, t2l, w3h, w3l, HID, 0, 0,
                                          nullptr, fh, fl, b3, 0, HID);

  // scores: S[b] = fa[b] @ fb[b]^T, 2-pass, NT=256
  const h16* fah = fh;
  const h16* fal = fl;
  const h16* fbh = fh + (size_t)MTOT * HID;
  gemm_mma<0, 2, 256><<<dim3(LB / 256, LA / 128, BATCH), 256, SM2>>>(
      fah, fal, fbh, nullptr, HID, (long long)LA * HID, (long long)LB * HID,
      S, nullptr, nullptr, nullptr, (long long)LA * LB, LB);

  // softmax: register-cached row softmax; col stats then transpose-normalize
  row_softmax_kernel<<<BATCH * LA, 256>>>();
  col_stats_kernel<<<dim3(LB / 128, BATCH), dim3(128, 8)>>>();
  k_pcolT<<<dim3(LB / 32, LA / 64, BATCH), t8>>>();

  // fused beta+alpha (1-pass, NT=256): z=0,1 beta; z=2,3 alpha -> 512 CTAs
  attn_fused<<<dim3(EMB / 256, LA / 128, 4), 256, SM1>>>(
      x2t, x1t, beta_out, alpha_out);
}

// round 13
// speedup vs baseline: 1.0469x; 1.0216x over previous
#include <cuda_runtime.h>
#include <cuda_fp16.h>
#include <stdint.h>
#include <math.h>

#define BATCH 2
#define LA 4096
#define LB 4096
#define EMB 1024
#define HID 1024
#define MTOT (BATCH * LA)
#define MALL (2 * MTOT)   // both MLPs merged: 16384 rows

typedef __half h16;

// ---------------- scratch (device globals: no alloc allowed) ----------------
__device__ h16 g_xh[(size_t)MALL * EMB], g_xl[(size_t)MALL * EMB];
__device__ h16 g_w1h[(size_t)HID * EMB], g_w1l[(size_t)HID * EMB];
__device__ h16 g_w2h[(size_t)HID * HID], g_w2l[(size_t)HID * HID];
__device__ h16 g_w3h[(size_t)HID * HID], g_w3l[(size_t)HID * HID];
__device__ h16 g_t1h[(size_t)MALL * HID], g_t1l[(size_t)MALL * HID];
__device__ h16 g_t2h[(size_t)MALL * HID], g_t2l[(size_t)MALL * HID];
__device__ h16 g_fh[(size_t)MALL * HID], g_fl[(size_t)MALL * HID];  // fa | fb
__device__ h16 g_x1t[(size_t)BATCH * EMB * LA];
__device__ h16 g_x2t[(size_t)BATCH * EMB * LB];
__device__ float g_S[(size_t)BATCH * LA * LB];
__device__ h16 g_pr[(size_t)BATCH * LA * LB];   // row-softmax(S)
__device__ h16 g_pc[(size_t)BATCH * LB * LA];   // col-softmax(S)^T
__device__ float g_mcol[BATCH * LB], g_izcol[BATCH * LB];
// per-(64-row-group, column) col-stat partials: [B][64][LB][m,z]
__device__ float g_cpart[(size_t)BATCH * 64 * LB * 2];

// ---------------- ptx helpers ------------------------------------------------
__device__ __forceinline__ uint32_t smem_u32(const void* p) {
  uint32_t a;
  asm("{ .reg .u64 t; cvta.to.shared.u64 t, %1; cvt.u32.u64 %0, t; }"
      : "=r"(a) : "l"(p));
  return a;
}
__device__ __forceinline__ void cp16(uint32_t d, const void* s) {
  asm volatile("cp.async.cg.shared.global [%0], [%1], 16;" :: "r"(d), "l"(s));
}
__device__ __forceinline__ void cp_commit() {
  asm volatile("cp.async.commit_group;");
}
template <int N>
__device__ __forceinline__ void cp_wait() {
  asm volatile("cp.async.wait_group %0;" :: "n"(N));
}
__device__ __forceinline__ void ldsm4(uint32_t* r, uint32_t a) {
  asm volatile("ldmatrix.sync.aligned.m8n8.x4.shared.b16 {%0,%1,%2,%3}, [%4];"
               : "=r"(r[0]), "=r"(r[1]), "=r"(r[2]), "=r"(r[3]) : "r"(a));
}
__device__ __forceinline__ void mma16816(float* d, const uint32_t* a, const uint32_t* b) {
  asm volatile(
      "mma.sync.aligned.m16n8k16.row.col.f32.f16.f16.f32 "
      "{%0,%1,%2,%3}, {%4,%5,%6,%7}, {%8,%9}, {%0,%1,%2,%3};"
      : "+f"(d[0]), "+f"(d[1]), "+f"(d[2]), "+f"(d[3])
      : "r"(a[0]), "r"(a[1]), "r"(a[2]), "r"(a[3]), "r"(b[0]), "r"(b[1]));
}

__device__ __forceinline__ void split_store(h16* oh, h16* ol, size_t o, float v) {
  h16 h = __float2half_rn(v);
  oh[o] = h;
  ol[o] = __float2half_rn(v - __half2float(h));
}
__device__ __forceinline__ void split2_store(h16* oh, h16* ol, size_t o,
                                             float v0, float v1) {
  h16 h0 = __float2half_rn(v0), h1 = __float2half_rn(v1);
  __half2 hp; hp.x = h0; hp.y = h1;
  __half2 lp;
  lp.x = __float2half_rn(v0 - __half2float(h0));
  lp.y = __float2half_rn(v1 - __half2float(h1));
  *(__half2*)(oh + o) = hp;
  *(__half2*)(ol + o) = lp;
}

// ---------------- mma.sync GEMM core: C[128 x NT] = A @ B^T ------------------
// PASSES=3: A pair, B pair. PASSES=2: A pair, B single. PASSES=1: singles.
// EPI 0: fp32 C. EPI 1: bias+relu -> fp16 pair. EPI 2: fp32 C + col partials.
static constexpr int LDM = 80;        // smem bytes per 32-h16 row (padded)

template <int PASSES, int NT>
static constexpr int smem_stage() {
  return ((PASSES >= 2) ? 2 : 1) * 128 * LDM + ((PASSES == 3) ? 2 : 1) * NT * LDM;
}
template <int PASSES, int NT>
static constexpr int smem_total() { return 3 * smem_stage<PASSES, NT>(); }

template <int EPI, int PASSES, int NT>
__device__ __forceinline__ void gemm_core(
    const h16* __restrict__ Ah, const h16* __restrict__ Al,
    const h16* __restrict__ Bh, const h16* __restrict__ Bl,
    int K, float* __restrict__ C, h16* __restrict__ Oh, h16* __restrict__ Ol,
    const float* __restrict__ bias, int ldc, float* __restrict__ cpart) {
  constexpr int NTA = (PASSES >= 2) ? 2 : 1;
  constexpr int NTB = (PASSES == 3) ? 2 : 1;
  constexpr int TA = 128 * LDM;
  constexpr int TB = NT * LDM;
  constexpr int STG = NTA * TA + NTB * TB;
  constexpr int AROWS = NTA * 128;
  constexpr int TROWS = AROWS + NTB * NT;
  constexpr int RPT = (TROWS + 255) / 256;  // loader iterations (ceil)
  constexpr int JN = NT / 64;               // B j-frags per warp
  extern __shared__ char smem[];
  const uint32_t sb = smem_u32(smem);
  const int tid = threadIdx.x;
  const int lane = tid & 31;
  const int wm = (tid >> 5) >> 2;   // 0..1
  const int wn = (tid >> 5) & 3;    // 0..3
  const size_t bm = (size_t)blockIdx.y * 128, bn = (size_t)blockIdx.x * NT;

  // -------- generalized loader: virtual rows [Ah | Al? | Bh | Bl?] ----------
  const h16* lp[RPT];
  uint32_t ls[RPT];
  bool lv[RPT];
#pragma unroll
  for (int r = 0; r < RPT; r++) {
    const int vr = tid + r * 256;
    lv[r] = (vr < TROWS);
    const h16* base;
    size_t row;
    if (vr < 128) { base = Ah; row = bm + vr; }
    else if (NTA == 2 && vr < 256) { base = Al; row = bm + (vr - 128); }
    else if (vr < TROWS) {
      const int rb = vr - AROWS;
      if (rb < NT) { base = Bh; row = bn + rb; }
      else         { base = Bl; row = bn + (rb - NT); }
    } else { base = Ah; row = bm; }  // dummy (guarded off)
    lp[r] = base + row * (size_t)K;
    ls[r] = sb + (uint32_t)((vr < TROWS ? vr : 0) * LDM);
  }

#define LOADST(c, s)                                                     \
  do {                                                                   \
    const uint32_t so_ = (uint32_t)(s) * STG;                            \
    const size_t ko_ = (size_t)(c) * 32;                                 \
    _Pragma("unroll") for (int r_ = 0; r_ < RPT; r_++)                   \
      if (lv[r_])                                                        \
        _Pragma("unroll") for (int ch_ = 0; ch_ < 4; ch_++)              \
            cp16(ls[r_] + so_ + ch_ * 16, lp[r_] + ko_ + ch_ * 8);       \
    cp_commit();                                                         \
  } while (0)

  // -------- fragment smem addresses (stage 0, kstep 0) ----------------------
  uint32_t aAh[4], aAl[4], aBh[JN], aBl[JN];
#pragma unroll
  for (int i = 0; i < 4; i++) {
    int row = wm * 64 + i * 16 + (lane & 15);
    uint32_t off = (uint32_t)(row * LDM + (lane >> 4) * 16);
    aAh[i] = sb + off;
    aAl[i] = sb + TA + off;
  }
#pragma unroll
  for (int j = 0; j < JN; j++) {
    int row = wn * (NT / 4) + j * 16 + (lane & 7) + ((lane >> 4) & 1) * 8;
    uint32_t off = (uint32_t)(row * LDM + ((lane >> 3) & 1) * 16);
    aBh[j] = sb + NTA * TA + off;
    aBl[j] = sb + NTA * TA + TB + off;
  }

  float acc[4][2 * JN][4];
#pragma unroll
  for (int i = 0; i < 4; i++)
#pragma unroll
    for (int j = 0; j < 2 * JN; j++)
#pragma unroll
      for (int r = 0; r < 4; r++) acc[i][j][r] = 0.f;

  const int NC = K >> 5;
  LOADST(0, 0);
  LOADST(1, 1);
  for (int c = 0; c < NC; c++) {
    if (c + 1 < NC) cp_wait<1>(); else cp_wait<0>();
    __syncthreads();
    if (c + 2 < NC) LOADST(c + 2, (c + 2) % 3);
    const uint32_t sbase = (uint32_t)(c % 3) * STG;
#pragma unroll
    for (int ks = 0; ks < 2; ks++) {
      const uint32_t soff = sbase + ks * 32;
      uint32_t fAh[4][4], fAl[4][4];
#pragma unroll
      for (int i = 0; i < 4; i++) {
        ldsm4(fAh[i], aAh[i] + soff);
        if (PASSES >= 2) ldsm4(fAl[i], aAl[i] + soff);
      }
#pragma unroll
      for (int j = 0; j < JN; j++) {
        uint32_t fBh[4], fBl[4];
        ldsm4(fBh, aBh[j] + soff);
        if (PASSES == 3) ldsm4(fBl, aBl[j] + soff);
#pragma unroll
        for (int i = 0; i < 4; i++)
#pragma unroll
          for (int hh = 0; hh < 2; hh++) {
            float* d = acc[i][j * 2 + hh];
            mma16816(d, fAh[i], &fBh[hh * 2]);
            if (PASSES == 3) mma16816(d, fAh[i], &fBl[hh * 2]);
            if (PASSES >= 2) mma16816(d, fAl[i], &fBh[hh * 2]);
          }
      }
    }
  }
#undef LOADST

  // epilogue: C / bias+relu stores
  const int l4 = lane >> 2, l2 = (lane & 3) * 2;
#pragma unroll
  for (int i = 0; i < 4; i++) {
#pragma unroll
    for (int j = 0; j < 2 * JN; j++) {
      const size_t row = bm + wm * 64 + i * 16 + l4;
      const size_t col = bn + wn * (NT / 4) + j * 8 + l2;
      float* a = acc[i][j];
      const size_t o = row * (size_t)ldc + col;
      if (EPI == 0 || EPI == 2) {
        float2 v0; v0.x = a[0]; v0.y = a[1];
        float2 v1; v1.x = a[2]; v1.y = a[3];
        *(float2*)(C + o) = v0;
        *(float2*)(C + o + 8 * (size_t)ldc) = v1;
      } else {
        float2 bv = *(const float2*)(bias + col);
        split2_store(Oh, Ol, o, fmaxf(a[0] + bv.x, 0.f), fmaxf(a[1] + bv.y, 0.f));
        split2_store(Oh, Ol, o + 8 * (size_t)ldc,
                     fmaxf(a[2] + bv.x, 0.f), fmaxf(a[3] + bv.y, 0.f));
      }
    }
  }

  // EPI 2: per-warp (64-row) column (m,z) partials -> cpart[group][col][2]
  if (EPI == 2) {
    const size_t grp = (size_t)(blockIdx.y * 2 + wm);
#pragma unroll
    for (int j = 0; j < 2 * JN; j++) {
#pragma unroll
      for (int hh = 0; hh < 2; hh++) {
        // thread-local max over its 8 rows of this column
        float m = acc[0][j][hh];
#pragma unroll
        for (int i = 0; i < 4; i++)
          m = fmaxf(m, fmaxf(acc[i][j][hh], acc[i][j][hh + 2]));
        // warp max across l4 (lanes sharing lane&3)
#pragma unroll
        for (int ofs = 4; ofs < 32; ofs <<= 1)
          m = fmaxf(m, __shfl_xor_sync(0xFFFFFFFFu, m, ofs));
        // exp-sum vs 64-row max
        float z = 0.f;
#pragma unroll
        for (int i = 0; i < 4; i++)
          z += __expf(acc[i][j][hh] - m) + __expf(acc[i][j][hh + 2] - m);
#pragma unroll
        for (int ofs = 4; ofs < 32; ofs <<= 1)
          z += __shfl_xor_sync(0xFFFFFFFFu, z, ofs);
        if (lane < 4) {
          const size_t col = bn + wn * (NT / 4) + j * 8 + (lane & 3) * 2 + hh;
          float2 mz; mz.x = m; mz.y = z;
          *(float2*)(cpart + (grp * LB + col) * 2) = mz;
        }
      }
    }
  }
}

// generic wrapper (per-batch strides)
template <int EPI, int PASSES, int NT>
__global__ void __launch_bounds__(256, 1) gemm_mma(
    const h16* Ah, const h16* Al, const h16* Bh, const h16* Bl,
    int K, long long sA, long long sB,
    float* C, h16* Oh, h16* Ol, const float* bias, long long sC, int ldc,
    float* cpart) {
  const size_t b = blockIdx.z;
  gemm_core<EPI, PASSES, NT>(
      Ah + b * sA, (PASSES >= 2) ? Al + b * sA : nullptr, Bh + b * sB,
      (PASSES == 3) ? Bl + b * sB : nullptr, K,
      (EPI != 1) ? C + b * sC : nullptr,
      (EPI == 1) ? Oh + b * sC : nullptr,
      (EPI == 1) ? Ol + b * sC : nullptr, bias, ldc,
      (EPI == 2) ? cpart + b * (size_t)64 * LB * 2 : nullptr);
}

// fused beta+alpha, 1-pass NT=256: z=0,1 -> beta batches; z=2,3 -> alpha
__global__ void __launch_bounds__(256, 1) attn_fused(
    const h16* __restrict__ x2t, const h16* __restrict__ x1t,
    float* __restrict__ beta, float* __restrict__ alpha) {
  const int z = blockIdx.z;
  const h16 *A, *Bh;
  float* C;
  if (z < 2) {
    A = g_pr + (size_t)z * LA * LB;
    Bh = x2t + (size_t)z * EMB * LB;
    C = beta + (size_t)z * LA * EMB;
  } else {
    const int b = z - 2;
    A = g_pc + (size_t)b * LB * LA;
    Bh = x1t + (size_t)b * EMB * LA;
    C = alpha + (size_t)b * LB * EMB;
  }
  gemm_core<0, 1, 256>(A, nullptr, Bh, nullptr, LB, C, nullptr, nullptr,
                       nullptr, EMB, nullptr);
}

// ---------------- conversion kernels -----------------------------------------
__global__ void k_prep(const float* __restrict__ in, h16* __restrict__ oh,
                       h16* __restrict__ ol, h16* __restrict__ ot, int L) {
  __shared__ float t[64][33];
  const int b = blockIdx.z;
  const int r0 = blockIdx.y * 64, c0 = blockIdx.x * 32;
  const int tx = threadIdx.x, ty = threadIdx.y;
  const float* pin = in + (size_t)b * L * EMB;
#pragma unroll
  for (int k = 0; k < 8; k++) {
    const int r = r0 + ty + 8 * k;
    float v = pin[(size_t)r * EMB + c0 + tx];
    t[ty + 8 * k][tx] = v;
    split_store(oh, ol, (size_t)(b * L + r) * EMB + c0 + tx, v);
  }
  __syncthreads();
#pragma unroll
  for (int k = 0; k < 4; k++) {
    const int c = c0 + ty + 8 * k;
    __half2 h = __floats2half2_rn(t[2 * tx][ty + 8 * k], t[2 * tx + 1][ty + 8 * k]);
    *(__half2*)(ot + (size_t)b * EMB * L + (size_t)c * L + r0 + 2 * tx) = h;
  }
}

__global__ void k_tsplit(const float* __restrict__ in, h16* __restrict__ oh,
                         h16* __restrict__ ol, int R, int Cc) {
  __shared__ float t[32][33];
  const int r0 = blockIdx.y * 32, c0 = blockIdx.x * 32;
  const int tx = threadIdx.x, ty = threadIdx.y;
#pragma unroll
  for (int k = 0; k < 4; k++)
    t[ty + 8 * k][tx] = in[(size_t)(r0 + ty + 8 * k) * Cc + c0 + tx];
  __syncthreads();
#pragma unroll
  for (int k = 0; k < 4; k++) {
    float v = t[tx][ty + 8 * k];
    size_t o = (size_t)(c0 + ty + 8 * k) * R + r0 + tx;
    split_store(oh, ol, o, v);
  }
}

// ---------------- softmax -----------------------------------------------------
__device__ __forceinline__ void olcomb(float& m, float& z, float m2, float z2) {
  if (m2 > m) { z = z * __expf(m - m2) + z2; m = m2; }
  else        { z = z + z2 * __expf(m2 - m); }
}

// row softmax, register-cached 3-phase: 1 S read, 1 exp per element.
__global__ void row_softmax_kernel() {
  const int row = blockIdx.x;
  const float4* s4 = (const float4*)(g_S + (size_t)row * LB);
  float4 v[4];
#pragma unroll
  for (int q = 0; q < 4; q++) v[q] = s4[threadIdx.x + q * 256];

  float m = v[0].x;
#pragma unroll
  for (int q = 0; q < 4; q++)
    m = fmaxf(m, fmaxf(fmaxf(v[q].x, v[q].y), fmaxf(v[q].z, v[q].w)));
  __shared__ float sm[256];
  sm[threadIdx.x] = m;
  __syncthreads();
  for (int st = 128; st > 0; st >>= 1) {
    if (threadIdx.x < st)
      sm[threadIdx.x] = fmaxf(sm[threadIdx.x], sm[threadIdx.x + st]);
    __syncthreads();
  }
  const float mm = sm[0];
  __syncthreads();

  float z = 0.f;
#pragma unroll
  for (int q = 0; q < 4; q++) {
    v[q].x = __expf(v[q].x - mm); v[q].y = __expf(v[q].y - mm);
    v[q].z = __expf(v[q].z - mm); v[q].w = __expf(v[q].w - mm);
    z += (v[q].x + v[q].y) + (v[q].z + v[q].w);
  }
  __shared__ float sz[256];
  sz[threadIdx.x] = z;
  __syncthreads();
  for (int st = 128; st > 0; st >>= 1) {
    if (threadIdx.x < st)
      sz[threadIdx.x] += sz[threadIdx.x + st];
    __syncthreads();
  }
  const float iz = 1.f / sz[0];

  uint2* p = (uint2*)(g_pr + (size_t)row * LB);
#pragma unroll
  for (int q = 0; q < 4; q++) {
    __half2 h01 = __floats2half2_rn(v[q].x * iz, v[q].y * iz);
    __half2 h23 = __floats2half2_rn(v[q].z * iz, v[q].w * iz);
    uint2 w;
    w.x = *(uint32_t*)&h01;
    w.y = *(uint32_t*)&h23;
    p[threadIdx.x + q * 256] = w;
  }
}

// combine 64 per-group column partials -> g_mcol, g_izcol
__global__ void col_combine_kernel() {
  const int b = blockIdx.y;
  const int col = blockIdx.x * 256 + threadIdx.x;
  const float2* p = (const float2*)(g_cpart + (size_t)b * 64 * LB * 2);
  float m = -3.0e38f, z = 0.f;
#pragma unroll 4
  for (int g = 0; g < 64; g++) {
    float2 mz = p[(size_t)g * LB + col];
    olcomb(m, z, mz.x, mz.y);
  }
  g_mcol[b * LB + col] = m;
  g_izcol[b * LB + col] = 1.f / z;
}

// col-softmax + transpose -> g_pc (fp16). block (32,8); tile 64 i x 32 j.
__global__ void k_pcolT() {
  __shared__ float t[64][33];
  const int b = blockIdx.z;
  const int i0 = blockIdx.y * 64, j0 = blockIdx.x * 32;
  const int tx = threadIdx.x, ty = threadIdx.y;
  const float* S = g_S + (size_t)b * LA * LB;
#pragma unroll
  for (int k = 0; k < 8; k++)
    t[ty + 8 * k][tx] = S[(size_t)(i0 + ty + 8 * k) * LB + j0 + tx];
  __syncthreads();
#pragma unroll
  for (int k = 0; k < 4; k++) {
    const int j = j0 + ty + 8 * k;
    const float m = g_mcol[b * LB + j], iz = g_izcol[b * LB + j];
    float p0 = __expf(t[2 * tx][ty + 8 * k] - m) * iz;
    float p1 = __expf(t[2 * tx + 1][ty + 8 * k] - m) * iz;
    __half2 h = __floats2half2_rn(p0, p1);
    *(__half2*)(g_pc + (size_t)b * LB * LA + (size_t)j * LA + i0 + 2 * tx) = h;
  }
}

// ---------------- launch -----------------------------------------------------
#define GSA(T, v, sym) T* v; cudaGetSymbolAddress((void**)&v, sym)

extern "C" void kernel_launch(void* const* d_in, const int* in_sizes, int n_in,
                              void* d_out, int out_size) {
  const float* x1 = (const float*)d_in[0];
  const float* x2 = (const float*)d_in[1];
  const float* W1 = (const float*)d_in[2];
  const float* b1 = (const float*)d_in[3];
  const float* W2 = (const float*)d_in[4];
  const float* b2 = (const float*)d_in[5];
  const float* W3 = (const float*)d_in[6];
  const float* b3 = (const float*)d_in[7];
  float* out = (float*)d_out;
  float* alpha_out = out;                             // [B, LB, EMB]
  float* beta_out = out + (size_t)BATCH * LB * EMB;   // [B, LA, EMB]

  GSA(h16, xh, g_xh); GSA(h16, xl, g_xl);
  GSA(h16, w1h, g_w1h); GSA(h16, w1l, g_w1l);
  GSA(h16, w2h, g_w2h); GSA(h16, w2l, g_w2l);
  GSA(h16, w3h, g_w3h); GSA(h16, w3l, g_w3l);
  GSA(h16, t1h, g_t1h); GSA(h16, t1l, g_t1l);
  GSA(h16, t2h, g_t2h); GSA(h16, t2l, g_t2l);
  GSA(h16, fh, g_fh); GSA(h16, fl, g_fl);
  GSA(h16, x1t, g_x1t); GSA(h16, x2t, g_x2t);
  GSA(float, S, g_S);
  GSA(float, cpart, g_cpart);

  constexpr int SM3 = smem_total<3, 256>();   // 184320
  constexpr int SM2 = smem_total<2, 256>();   // 122880
  constexpr int SM1 = smem_total<1, 256>();   // 92160
  cudaFuncSetAttribute(gemm_mma<1, 3, 256>, cudaFuncAttributeMaxDynamicSharedMemorySize, SM3);
  cudaFuncSetAttribute(gemm_mma<2, 2, 256>, cudaFuncAttributeMaxDynamicSharedMemorySize, SM2);
  cudaFuncSetAttribute(attn_fused, cudaFuncAttributeMaxDynamicSharedMemorySize, SM1);

  const size_t nx = (size_t)MTOT * EMB;
  dim3 t8(32, 8);

  // fused input prep: x1 -> rows [0, 8192) + x1t ; x2 -> rows [8192, 16384) + x2t
  k_prep<<<dim3(EMB / 32, LA / 64, BATCH), t8>>>(x1, xh, xl, x1t, LA);
  k_prep<<<dim3(EMB / 32, LB / 64, BATCH), t8>>>(x2, xh + nx, xl + nx, x2t, LB);
  k_tsplit<<<dim3(HID / 32, EMB / 32), t8>>>(W1, w1h, w1l, EMB, HID);
  k_tsplit<<<dim3(HID / 32, HID / 32), t8>>>(W2, w2h, w2l, HID, HID);
  k_tsplit<<<dim3(HID / 32, HID / 32), t8>>>(W3, w3h, w3l, HID, HID);

  // merged MLP (both inputs, both batches): M = 16384, 3-pass, NT=256
  dim3 gMLP(HID / 256, MALL / 128, 1);  // (4, 128) = 512 CTAs
  gemm_mma<1, 3, 256><<<gMLP, 256, SM3>>>(xh, xl, w1h, w1l, EMB, 0, 0,
                                          nullptr, t1h, t1l, b1, 0, HID, nullptr);
  gemm_mma<1, 3, 256><<<gMLP, 256, SM3>>>(t1h, t1l, w2h, w2l, HID, 0, 0,
                                          nullptr, t2h, t2l, b2, 0, HID, nullptr);
  gemm_mma<1, 3, 256><<<gMLP, 256, SM3>>>(t2h, t2l, w3h, w3l, HID, 0, 0,
                                          nullptr, fh, fl, b3, 0, HID, nullptr);

  // scores: S[b] = fa[b] @ fb[b]^T, 2-pass, NT=256, EPI2 (+ column partials)
  const h16* fah = fh;
  const h16* fal = fl;
  const h16* fbh = fh + (size_t)MTOT * HID;
  gemm_mma<2, 2, 256><<<dim3(LB / 256, LA / 128, BATCH), 256, SM2>>>(
      fah, fal, fbh, nullptr, HID, (long long)LA * HID, (long long)LB * HID,
      S, nullptr, nullptr, nullptr, (long long)LA * LB, LB, cpart);

  // softmax: row softmax; column stats from GEMM partials; transpose-normalize
  row_softmax_kernel<<<BATCH * LA, 256>>>();
  col_combine_kernel<<<dim3(LB / 256, BATCH), 256>>>();
  k_pcolT<<<dim3(LB / 32, LA / 64, BATCH), t8>>>();

  // fused beta+alpha (1-pass, NT=256): z=0,1 beta; z=2,3 alpha -> 512 CTAs
  attn_fused<<<dim3(EMB / 256, LA / 128, 4), 256, SM1>>>(
      x2t, x1t, beta_out, alpha_out);
}

// round 14
// speedup vs baseline: 1.1340x; 1.0831x over previous
#include <cuda_runtime.h>
#include <cuda_fp16.h>
#include <stdint.h>
#include <math.h>

#define BATCH 2
#define LA 4096
#define LB 4096
#define EMB 1024
#define HID 1024
#define MTOT (BATCH * LA)
#define MALL (2 * MTOT)   // both MLPs merged: 16384 rows

typedef __half h16;

// ---------------- scratch (device globals: no alloc allowed) ----------------
__device__ h16 g_xh[(size_t)MALL * EMB], g_xl[(size_t)MALL * EMB];
__device__ h16 g_w1h[(size_t)HID * EMB], g_w1l[(size_t)HID * EMB];
__device__ h16 g_w2h[(size_t)HID * HID], g_w2l[(size_t)HID * HID];
__device__ h16 g_w3h[(size_t)HID * HID], g_w3l[(size_t)HID * HID];
__device__ h16 g_t1h[(size_t)MALL * HID], g_t1l[(size_t)MALL * HID];
__device__ h16 g_t2h[(size_t)MALL * HID], g_t2l[(size_t)MALL * HID];
__device__ h16 g_fh[(size_t)MALL * HID], g_fl[(size_t)MALL * HID];  // fa | fb
__device__ h16 g_x1t[(size_t)BATCH * EMB * LA];
__device__ h16 g_x2t[(size_t)BATCH * EMB * LB];
__device__ float g_S[(size_t)BATCH * LA * LB];
__device__ h16 g_pr[(size_t)BATCH * LA * LB];   // row-softmax(S)
__device__ h16 g_pc[(size_t)BATCH * LB * LA];   // col-softmax(S)^T
__device__ float g_mcol[BATCH * LB], g_izcol[BATCH * LB];
__device__ float g_cpart[(size_t)BATCH * 64 * LB * 2];  // col-stat partials
__device__ int g_sync[3 * 128];                 // per (layer, row-block) counters

// ---------------- ptx helpers ------------------------------------------------
__device__ __forceinline__ uint32_t smem_u32(const void* p) {
  uint32_t a;
  asm("{ .reg .u64 t; cvta.to.shared.u64 t, %1; cvt.u32.u64 %0, t; }"
      : "=r"(a) : "l"(p));
  return a;
}
__device__ __forceinline__ void cp16(uint32_t d, const void* s) {
  asm volatile("cp.async.cg.shared.global [%0], [%1], 16;" :: "r"(d), "l"(s));
}
__device__ __forceinline__ void cp_commit() {
  asm volatile("cp.async.commit_group;");
}
template <int N>
__device__ __forceinline__ void cp_wait() {
  asm volatile("cp.async.wait_group %0;" :: "n"(N));
}
__device__ __forceinline__ void ldsm4(uint32_t* r, uint32_t a) {
  asm volatile("ldmatrix.sync.aligned.m8n8.x4.shared.b16 {%0,%1,%2,%3}, [%4];"
               : "=r"(r[0]), "=r"(r[1]), "=r"(r[2]), "=r"(r[3]) : "r"(a));
}
__device__ __forceinline__ void mma16816(float* d, const uint32_t* a, const uint32_t* b) {
  asm volatile(
      "mma.sync.aligned.m16n8k16.row.col.f32.f16.f16.f32 "
      "{%0,%1,%2,%3}, {%4,%5,%6,%7}, {%8,%9}, {%0,%1,%2,%3};"
      : "+f"(d[0]), "+f"(d[1]), "+f"(d[2]), "+f"(d[3])
      : "r"(a[0]), "r"(a[1]), "r"(a[2]), "r"(a[3]), "r"(b[0]), "r"(b[1]));
}

__device__ __forceinline__ void split_store(h16* oh, h16* ol, size_t o, float v) {
  h16 h = __float2half_rn(v);
  oh[o] = h;
  ol[o] = __float2half_rn(v - __half2float(h));
}
__device__ __forceinline__ void split2_store(h16* oh, h16* ol, size_t o,
                                             float v0, float v1) {
  h16 h0 = __float2half_rn(v0), h1 = __float2half_rn(v1);
  __half2 hp; hp.x = h0; hp.y = h1;
  __half2 lp;
  lp.x = __float2half_rn(v0 - __half2float(h0));
  lp.y = __float2half_rn(v1 - __half2float(h1));
  *(__half2*)(oh + o) = hp;
  *(__half2*)(ol + o) = lp;
}

// ---------------- mma.sync GEMM core: C[128 x NT] = A @ B^T ------------------
// PASSES=3: A pair, B pair. PASSES=2: A pair, B single. PASSES=1: singles.
// EPI 0: fp32 C. EPI 1: bias+relu -> fp16 pair. EPI 2: fp32 C + col partials.
static constexpr int LDM = 80;        // smem bytes per 32-h16 row (padded)

template <int PASSES, int NT>
static constexpr int smem_stage() {
  return ((PASSES >= 2) ? 2 : 1) * 128 * LDM + ((PASSES == 3) ? 2 : 1) * NT * LDM;
}
template <int PASSES, int NT>
static constexpr int smem_total() { return 3 * smem_stage<PASSES, NT>(); }

template <int EPI, int PASSES, int NT>
__device__ __forceinline__ void gemm_core(
    const h16* __restrict__ Ah, const h16* __restrict__ Al,
    const h16* __restrict__ Bh, const h16* __restrict__ Bl,
    int K, float* __restrict__ C, h16* __restrict__ Oh, h16* __restrict__ Ol,
    const float* __restrict__ bias, int ldc, float* __restrict__ cpart,
    int bx, int by) {
  constexpr int NTA = (PASSES >= 2) ? 2 : 1;
  constexpr int NTB = (PASSES == 3) ? 2 : 1;
  constexpr int TA = 128 * LDM;
  constexpr int TB = NT * LDM;
  constexpr int STG = NTA * TA + NTB * TB;
  constexpr int AROWS = NTA * 128;
  constexpr int TROWS = AROWS + NTB * NT;
  constexpr int RPT = (TROWS + 255) / 256;  // loader iterations (ceil)
  constexpr int JN = NT / 64;               // B j-frags per warp
  extern __shared__ char smem[];
  const uint32_t sb = smem_u32(smem);
  const int tid = threadIdx.x;
  const int lane = tid & 31;
  const int wm = (tid >> 5) >> 2;   // 0..1
  const int wn = (tid >> 5) & 3;    // 0..3
  const size_t bm = (size_t)by * 128, bn = (size_t)bx * NT;

  // -------- generalized loader: virtual rows [Ah | Al? | Bh | Bl?] ----------
  const h16* lp[RPT];
  uint32_t ls[RPT];
  bool lv[RPT];
#pragma unroll
  for (int r = 0; r < RPT; r++) {
    const int vr = tid + r * 256;
    lv[r] = (vr < TROWS);
    const h16* base;
    size_t row;
    if (vr < 128) { base = Ah; row = bm + vr; }
    else if (NTA == 2 && vr < 256) { base = Al; row = bm + (vr - 128); }
    else if (vr < TROWS) {
      const int rb = vr - AROWS;
      if (rb < NT) { base = Bh; row = bn + rb; }
      else         { base = Bl; row = bn + (rb - NT); }
    } else { base = Ah; row = bm; }  // dummy (guarded off)
    lp[r] = base + row * (size_t)K;
    ls[r] = sb + (uint32_t)((vr < TROWS ? vr : 0) * LDM);
  }

#define LOADST(c, s)                                                     \
  do {                                                                   \
    const uint32_t so_ = (uint32_t)(s) * STG;                            \
    const size_t ko_ = (size_t)(c) * 32;                                 \
    _Pragma("unroll") for (int r_ = 0; r_ < RPT; r_++)                   \
      if (lv[r_])                                                        \
        _Pragma("unroll") for (int ch_ = 0; ch_ < 4; ch_++)              \
            cp16(ls[r_] + so_ + ch_ * 16, lp[r_] + ko_ + ch_ * 8);       \
    cp_commit();                                                         \
  } while (0)

  // -------- fragment smem addresses (stage 0, kstep 0) ----------------------
  uint32_t aAh[4], aAl[4], aBh[JN], aBl[JN];
#pragma unroll
  for (int i = 0; i < 4; i++) {
    int row = wm * 64 + i * 16 + (lane & 15);
    uint32_t off = (uint32_t)(row * LDM + (lane >> 4) * 16);
    aAh[i] = sb + off;
    aAl[i] = sb + TA + off;
  }
#pragma unroll
  for (int j = 0; j < JN; j++) {
    int row = wn * (NT / 4) + j * 16 + (lane & 7) + ((lane >> 4) & 1) * 8;
    uint32_t off = (uint32_t)(row * LDM + ((lane >> 3) & 1) * 16);
    aBh[j] = sb + NTA * TA + off;
    aBl[j] = sb + NTA * TA + TB + off;
  }

  float acc[4][2 * JN][4];
#pragma unroll
  for (int i = 0; i < 4; i++)
#pragma unroll
    for (int j = 0; j < 2 * JN; j++)
#pragma unroll
      for (int r = 0; r < 4; r++) acc[i][j][r] = 0.f;

  const int NC = K >> 5;
  LOADST(0, 0);
  LOADST(1, 1);
  for (int c = 0; c < NC; c++) {
    if (c + 1 < NC) cp_wait<1>(); else cp_wait<0>();
    __syncthreads();
    if (c + 2 < NC) LOADST(c + 2, (c + 2) % 3);
    const uint32_t sbase = (uint32_t)(c % 3) * STG;
#pragma unroll
    for (int ks = 0; ks < 2; ks++) {
      const uint32_t soff = sbase + ks * 32;
      uint32_t fAh[4][4], fAl[4][4];
#pragma unroll
      for (int i = 0; i < 4; i++) {
        ldsm4(fAh[i], aAh[i] + soff);
        if (PASSES >= 2) ldsm4(fAl[i], aAl[i] + soff);
      }
#pragma unroll
      for (int j = 0; j < JN; j++) {
        uint32_t fBh[4], fBl[4];
        ldsm4(fBh, aBh[j] + soff);
        if (PASSES == 3) ldsm4(fBl, aBl[j] + soff);
#pragma unroll
        for (int i = 0; i < 4; i++)
#pragma unroll
          for (int hh = 0; hh < 2; hh++) {
            float* d = acc[i][j * 2 + hh];
            mma16816(d, fAh[i], &fBh[hh * 2]);
            if (PASSES == 3) mma16816(d, fAh[i], &fBl[hh * 2]);
            if (PASSES >= 2) mma16816(d, fAl[i], &fBh[hh * 2]);
          }
      }
    }
  }
#undef LOADST

  // epilogue: C / bias+relu stores
  const int l4 = lane >> 2, l2 = (lane & 3) * 2;
#pragma unroll
  for (int i = 0; i < 4; i++) {
#pragma unroll
    for (int j = 0; j < 2 * JN; j++) {
      const size_t row = bm + wm * 64 + i * 16 + l4;
      const size_t col = bn + wn * (NT / 4) + j * 8 + l2;
      float* a = acc[i][j];
      const size_t o = row * (size_t)ldc + col;
      if (EPI == 0 || EPI == 2) {
        float2 v0; v0.x = a[0]; v0.y = a[1];
        float2 v1; v1.x = a[2]; v1.y = a[3];
        *(float2*)(C + o) = v0;
        *(float2*)(C + o + 8 * (size_t)ldc) = v1;
      } else {
        float2 bv = *(const float2*)(bias + col);
        split2_store(Oh, Ol, o, fmaxf(a[0] + bv.x, 0.f), fmaxf(a[1] + bv.y, 0.f));
        split2_store(Oh, Ol, o + 8 * (size_t)ldc,
                     fmaxf(a[2] + bv.x, 0.f), fmaxf(a[3] + bv.y, 0.f));
      }
    }
  }

  // EPI 2: per-warp (64-row) column (m,z) partials -> cpart[group][col][2]
  if (EPI == 2) {
    const size_t grp = (size_t)(by * 2 + wm);
#pragma unroll
    for (int j = 0; j < 2 * JN; j++) {
#pragma unroll
      for (int hh = 0; hh < 2; hh++) {
        float m = acc[0][j][hh];
#pragma unroll
        for (int i = 0; i < 4; i++)
          m = fmaxf(m, fmaxf(acc[i][j][hh], acc[i][j][hh + 2]));
#pragma unroll
        for (int ofs = 4; ofs < 32; ofs <<= 1)
          m = fmaxf(m, __shfl_xor_sync(0xFFFFFFFFu, m, ofs));
        float z = 0.f;
#pragma unroll
        for (int i = 0; i < 4; i++)
          z += __expf(acc[i][j][hh] - m) + __expf(acc[i][j][hh + 2] - m);
#pragma unroll
        for (int ofs = 4; ofs < 32; ofs <<= 1)
          z += __shfl_xor_sync(0xFFFFFFFFu, z, ofs);
        if (lane < 4) {
          const size_t col = bn + wn * (NT / 4) + j * 8 + (lane & 3) * 2 + hh;
          float2 mz; mz.x = m; mz.y = z;
          *(float2*)(cpart + (grp * LB + col) * 2) = mz;
        }
      }
    }
  }
}

// ---------------- mega kernel: 3 MLP layers + scores, flag-synced ------------
// bids 0..1535: MLP layer L = bid/512, tile t = bid%512, bx = t&3, by = t>>2.
// bids 1536..2559: scores, t = bid-1536, b = t>>9, bx = (t&511)&15, by = (t&511)>>4.
__global__ void __launch_bounds__(256, 1) mega_kernel(
    const float* __restrict__ b1, const float* __restrict__ b2,
    const float* __restrict__ b3) {
  const int bid = blockIdx.x;
  if (bid < 1536) {
    const int L = bid >> 9;
    const int t = bid & 511;
    const int bx = t & 3;
    const int by = t >> 2;
    if (L > 0) {
      if (threadIdx.x == 0) {
        volatile int* f = &g_sync[(L - 1) * 128 + by];
        while (*f < 4) {}
      }
      __syncthreads();
      __threadfence();
    }
    const h16 *Ah, *Al, *Bh, *Bl;
    h16 *Oh, *Ol;
    const float* bias;
    if (L == 0) { Ah = g_xh;  Al = g_xl;  Bh = g_w1h; Bl = g_w1l;
                  Oh = g_t1h; Ol = g_t1l; bias = b1; }
    else if (L == 1) { Ah = g_t1h; Al = g_t1l; Bh = g_w2h; Bl = g_w2l;
                       Oh = g_t2h; Ol = g_t2l; bias = b2; }
    else { Ah = g_t2h; Al = g_t2l; Bh = g_w3h; Bl = g_w3l;
           Oh = g_fh;  Ol = g_fl;  bias = b3; }
    gemm_core<1, 3, 256>(Ah, Al, Bh, Bl, HID, nullptr, Oh, Ol, bias, HID,
                         nullptr, bx, by);
    __syncthreads();
    if (threadIdx.x == 0) {
      __threadfence();
      atomicAdd(&g_sync[L * 128 + by], 1);
    }
  } else {
    const int t = bid - 1536;
    const int b = t >> 9;
    const int tt = t & 511;
    const int bx = tt & 15;
    const int by = tt >> 4;
    // wait: fa row-block b*32+by; fb row-blocks 64+b*32+bx*2, +1 (layer 2)
    if (threadIdx.x < 3) {
      int idx;
      if (threadIdx.x == 0) idx = 2 * 128 + b * 32 + by;
      else if (threadIdx.x == 1) idx = 2 * 128 + 64 + b * 32 + bx * 2;
      else idx = 2 * 128 + 64 + b * 32 + bx * 2 + 1;
      volatile int* f = &g_sync[idx];
      while (*f < 4) {}
    }
    __syncthreads();
    __threadfence();
    gemm_core<2, 2, 256>(
        g_fh + (size_t)b * LA * HID, g_fl + (size_t)b * LA * HID,
        g_fh + (size_t)(MTOT + b * LB) * HID, nullptr, HID,
        g_S + (size_t)b * LA * LB, nullptr, nullptr, nullptr, LB,
        g_cpart + (size_t)b * 64 * LB * 2, bx, by);
  }
}

// fused beta+alpha, 1-pass NT=256: z=0,1 -> beta batches; z=2,3 -> alpha
__global__ void __launch_bounds__(256, 1) attn_fused(
    const h16* __restrict__ x2t, const h16* __restrict__ x1t,
    float* __restrict__ beta, float* __restrict__ alpha) {
  const int z = blockIdx.z;
  const h16 *A, *Bh;
  float* C;
  if (z < 2) {
    A = g_pr + (size_t)z * LA * LB;
    Bh = x2t + (size_t)z * EMB * LB;
    C = beta + (size_t)z * LA * EMB;
  } else {
    const int b = z - 2;
    A = g_pc + (size_t)b * LB * LA;
    Bh = x1t + (size_t)b * EMB * LA;
    C = alpha + (size_t)b * LB * EMB;
  }
  gemm_core<0, 1, 256>(A, nullptr, Bh, nullptr, LB, C, nullptr, nullptr,
                       nullptr, EMB, nullptr, blockIdx.x, blockIdx.y);
}

// ---------------- conversion kernels -----------------------------------------
__global__ void k_prep(const float* __restrict__ in, h16* __restrict__ oh,
                       h16* __restrict__ ol, h16* __restrict__ ot, int L) {
  __shared__ float t[64][33];
  const int b = blockIdx.z;
  const int r0 = blockIdx.y * 64, c0 = blockIdx.x * 32;
  const int tx = threadIdx.x, ty = threadIdx.y;
  const float* pin = in + (size_t)b * L * EMB;
#pragma unroll
  for (int k = 0; k < 8; k++) {
    const int r = r0 + ty + 8 * k;
    float v = pin[(size_t)r * EMB + c0 + tx];
    t[ty + 8 * k][tx] = v;
    split_store(oh, ol, (size_t)(b * L + r) * EMB + c0 + tx, v);
  }
  __syncthreads();
#pragma unroll
  for (int k = 0; k < 4; k++) {
    const int c = c0 + ty + 8 * k;
    __half2 h = __floats2half2_rn(t[2 * tx][ty + 8 * k], t[2 * tx + 1][ty + 8 * k]);
    *(__half2*)(ot + (size_t)b * EMB * L + (size_t)c * L + r0 + 2 * tx) = h;
  }
}

__global__ void k_tsplit(const float* __restrict__ in, h16* __restrict__ oh,
                         h16* __restrict__ ol, int R, int Cc) {
  __shared__ float t[32][33];
  const int r0 = blockIdx.y * 32, c0 = blockIdx.x * 32;
  const int tx = threadIdx.x, ty = threadIdx.y;
#pragma unroll
  for (int k = 0; k < 4; k++)
    t[ty + 8 * k][tx] = in[(size_t)(r0 + ty + 8 * k) * Cc + c0 + tx];
  __syncthreads();
#pragma unroll
  for (int k = 0; k < 4; k++) {
    float v = t[tx][ty + 8 * k];
    size_t o = (size_t)(c0 + ty + 8 * k) * R + r0 + tx;
    split_store(oh, ol, o, v);
  }
}

// ---------------- softmax -----------------------------------------------------
__device__ __forceinline__ void olcomb(float& m, float& z, float m2, float z2) {
  if (m2 > m) { z = z * __expf(m - m2) + z2; m = m2; }
  else        { z = z + z2 * __expf(m2 - m); }
}

// row softmax, register-cached 3-phase: 1 S read, 1 exp per element.
__global__ void row_softmax_kernel() {
  const int row = blockIdx.x;
  const float4* s4 = (const float4*)(g_S + (size_t)row * LB);
  float4 v[4];
#pragma unroll
  for (int q = 0; q < 4; q++) v[q] = s4[threadIdx.x + q * 256];

  float m = v[0].x;
#pragma unroll
  for (int q = 0; q < 4; q++)
    m = fmaxf(m, fmaxf(fmaxf(v[q].x, v[q].y), fmaxf(v[q].z, v[q].w)));
  __shared__ float sm[256];
  sm[threadIdx.x] = m;
  __syncthreads();
  for (int st = 128; st > 0; st >>= 1) {
    if (threadIdx.x < st)
      sm[threadIdx.x] = fmaxf(sm[threadIdx.x], sm[threadIdx.x + st]);
    __syncthreads();
  }
  const float mm = sm[0];
  __syncthreads();

  float z = 0.f;
#pragma unroll
  for (int q = 0; q < 4; q++) {
    v[q].x = __expf(v[q].x - mm); v[q].y = __expf(v[q].y - mm);
    v[q].z = __expf(v[q].z - mm); v[q].w = __expf(v[q].w - mm);
    z += (v[q].x + v[q].y) + (v[q].z + v[q].w);
  }
  __shared__ float sz[256];
  sz[threadIdx.x] = z;
  __syncthreads();
  for (int st = 128; st > 0; st >>= 1) {
    if (threadIdx.x < st)
      sz[threadIdx.x] += sz[threadIdx.x + st];
    __syncthreads();
  }
  const float iz = 1.f / sz[0];

  uint2* p = (uint2*)(g_pr + (size_t)row * LB);
#pragma unroll
  for (int q = 0; q < 4; q++) {
    __half2 h01 = __floats2half2_rn(v[q].x * iz, v[q].y * iz);
    __half2 h23 = __floats2half2_rn(v[q].z * iz, v[q].w * iz);
    uint2 w;
    w.x = *(uint32_t*)&h01;
    w.y = *(uint32_t*)&h23;
    p[threadIdx.x + q * 256] = w;
  }
}

// combine 64 per-group column partials -> g_mcol, g_izcol
__global__ void col_combine_kernel() {
  const int b = blockIdx.y;
  const int col = blockIdx.x * 256 + threadIdx.x;
  const float2* p = (const float2*)(g_cpart + (size_t)b * 64 * LB * 2);
  float m = -3.0e38f, z = 0.f;
#pragma unroll 4
  for (int g = 0; g < 64; g++) {
    float2 mz = p[(size_t)g * LB + col];
    olcomb(m, z, mz.x, mz.y);
  }
  g_mcol[b * LB + col] = m;
  g_izcol[b * LB + col] = 1.f / z;
}

// col-softmax + transpose -> g_pc (fp16). block (32,8); tile 64 i x 32 j.
__global__ void k_pcolT() {
  __shared__ float t[64][33];
  const int b = blockIdx.z;
  const int i0 = blockIdx.y * 64, j0 = blockIdx.x * 32;
  const int tx = threadIdx.x, ty = threadIdx.y;
  const float* S = g_S + (size_t)b * LA * LB;
#pragma unroll
  for (int k = 0; k < 8; k++)
    t[ty + 8 * k][tx] = S[(size_t)(i0 + ty + 8 * k) * LB + j0 + tx];
  __syncthreads();
#pragma unroll
  for (int k = 0; k < 4; k++) {
    const int j = j0 + ty + 8 * k;
    const float m = g_mcol[b * LB + j], iz = g_izcol[b * LB + j];
    float p0 = __expf(t[2 * tx][ty + 8 * k] - m) * iz;
    float p1 = __expf(t[2 * tx + 1][ty + 8 * k] - m) * iz;
    __half2 h = __floats2half2_rn(p0, p1);
    *(__half2*)(g_pc + (size_t)b * LB * LA + (size_t)j * LA + i0 + 2 * tx) = h;
  }
}

// ---------------- launch -----------------------------------------------------
#define GSA(T, v, sym) T* v; cudaGetSymbolAddress((void**)&v, sym)

extern "C" void kernel_launch(void* const* d_in, const int* in_sizes, int n_in,
                              void* d_out, int out_size) {
  const float* x1 = (const float*)d_in[0];
  const float* x2 = (const float*)d_in[1];
  const float* W1 = (const float*)d_in[2];
  const float* b1 = (const float*)d_in[3];
  const float* W2 = (const float*)d_in[4];
  const float* b2 = (const float*)d_in[5];
  const float* W3 = (const float*)d_in[6];
  const float* b3 = (const float*)d_in[7];
  float* out = (float*)d_out;
  float* alpha_out = out;                             // [B, LB, EMB]
  float* beta_out = out + (size_t)BATCH * LB * EMB;   // [B, LA, EMB]

  GSA(h16, xh, g_xh); GSA(h16, xl, g_xl);
  GSA(h16, w1h, g_w1h); GSA(h16, w1l, g_w1l);
  GSA(h16, w2h, g_w2h); GSA(h16, w2l, g_w2l);
  GSA(h16, w3h, g_w3h); GSA(h16, w3l, g_w3l);
  GSA(h16, x1t, g_x1t); GSA(h16, x2t, g_x2t);
  GSA(int, sync_flags, g_sync);

  constexpr int SM3 = smem_total<3, 256>();   // 184320
  constexpr int SM1 = smem_total<1, 256>();   // 92160
  cudaFuncSetAttribute(mega_kernel, cudaFuncAttributeMaxDynamicSharedMemorySize, SM3);
  cudaFuncSetAttribute(attn_fused, cudaFuncAttributeMaxDynamicSharedMemorySize, SM1);

  const size_t nx = (size_t)MTOT * EMB;
  dim3 t8(32, 8);

  // zero dependency flags (graph-capturable; re-zeroed every replay)
  cudaMemsetAsync(sync_flags, 0, 3 * 128 * sizeof(int));

  // fused input prep: x1 -> rows [0, 8192) + x1t ; x2 -> rows [8192, 16384) + x2t
  k_prep<<<dim3(EMB / 32, LA / 64, BATCH), t8>>>(x1, xh, xl, x1t, LA);
  k_prep<<<dim3(EMB / 32, LB / 64, BATCH), t8>>>(x2, xh + nx, xl + nx, x2t, LB);
  k_tsplit<<<dim3(HID / 32, EMB / 32), t8>>>(W1, w1h, w1l, EMB, HID);
  k_tsplit<<<dim3(HID / 32, HID / 32), t8>>>(W2, w2h, w2l, HID, HID);
  k_tsplit<<<dim3(HID / 32, HID / 32), t8>>>(W3, w3h, w3l, HID, HID);

  // mega: 3 MLP layers (1536 CTAs) + scores (1024 CTAs), flag-synced
  mega_kernel<<<2560, 256, SM3>>>(b1, b2, b3);

  // softmax: row softmax; column stats from GEMM partials; transpose-normalize
  row_softmax_kernel<<<BATCH * LA, 256>>>();
  col_combine_kernel<<<dim3(LB / 256, BATCH), 256>>>();
  k_pcolT<<<dim3(LB / 32, LA / 64, BATCH), t8>>>();

  // fused beta+alpha (1-pass, NT=256): z=0,1 beta; z=2,3 alpha -> 512 CTAs
  attn_fused<<<dim3(EMB / 256, LA / 128, 4), 256, SM1>>>(
      x2t, x1t, beta_out, alpha_out);
}